// round 2
// baseline (speedup 1.0000x reference)
#include <cuda_runtime.h>
#include <cuda_fp16.h>
#include <cstdint>

#define B_      1024
#define N_      4096
#define L_      8
#define K_      16
#define G_      8            // batch rows per block
#define THREADS_ 1024        // 4096 / 1024 = 4 even n-iters per thread
#define NBLOCKS_ (B_ / G_)   // 128

// Packed uint16 indices (values in [0, 4096)): 8*4096*16*2 = 1 MB scratch.
__device__ __align__(16) uint16_t g_src16[L_ * N_ * K_];

__global__ void prep_src16(const int* __restrict__ src) {
    int i = blockIdx.x * blockDim.x + threadIdx.x;
    int base = i * 4;
    if (base < L_ * N_ * K_) {
        int4 v = *reinterpret_cast<const int4*>(src + base);
        ushort4 o = make_ushort4((uint16_t)v.x, (uint16_t)v.y,
                                 (uint16_t)v.z, (uint16_t)v.w);
        *reinterpret_cast<ushort4*>(g_src16 + base) = o;
    }
}

// One gather index serves all G=8 batch rows: one LDS.128 of [s][0..7] fp16,
// converted to fp32 and FMA'd into 8 accumulators.
__device__ __forceinline__ void gather_fma(const __half* __restrict__ cur,
                                           uint32_t s, float wk, float* acc) {
    uint4 v = *reinterpret_cast<const uint4*>(cur + s * G_);
    float2 f;
    f = __half22float2(*reinterpret_cast<__half2*>(&v.x));
    acc[0] = fmaf(f.x, wk, acc[0]); acc[1] = fmaf(f.y, wk, acc[1]);
    f = __half22float2(*reinterpret_cast<__half2*>(&v.y));
    acc[2] = fmaf(f.x, wk, acc[2]); acc[3] = fmaf(f.y, wk, acc[3]);
    f = __half22float2(*reinterpret_cast<__half2*>(&v.z));
    acc[4] = fmaf(f.x, wk, acc[4]); acc[5] = fmaf(f.y, wk, acc[5]);
    f = __half22float2(*reinterpret_cast<__half2*>(&v.w));
    acc[6] = fmaf(f.x, wk, acc[6]); acc[7] = fmaf(f.y, wk, acc[7]);
}

// Process 8 of the 16 k's: loads its own indices + weights right before use to
// keep the live register set small (fits the 64-reg budget at 1024 threads).
__device__ __forceinline__ void half_k(const __half* __restrict__ cur,
                                       uint4 s, const float4* __restrict__ wv,
                                       float* acc) {
    float4 wa = wv[0];
    gather_fma(cur, s.x & 0xFFFFu, wa.x, acc);
    gather_fma(cur, s.x >> 16,     wa.y, acc);
    gather_fma(cur, s.y & 0xFFFFu, wa.z, acc);
    gather_fma(cur, s.y >> 16,     wa.w, acc);
    float4 wb = wv[1];
    gather_fma(cur, s.z & 0xFFFFu, wb.x, acc);
    gather_fma(cur, s.z >> 16,     wb.y, acc);
    gather_fma(cur, s.w & 0xFFFFu, wb.z, acc);
    gather_fma(cur, s.w >> 16,     wb.w, acc);
}

__global__ void __launch_bounds__(THREADS_, 1)
genome_kernel(const float* __restrict__ x, const float* __restrict__ w,
              float* __restrict__ out) {
    extern __shared__ __half sm[];
    __half* bufA = sm;               // [N_][G_]
    __half* bufB = sm + N_ * G_;     // double buffer
    const int b0 = blockIdx.x * G_;

    // Load this block's 8 batch rows of x into bufA (fp16, [n][g] layout).
    for (int n = threadIdx.x; n < N_; n += THREADS_) {
        __half tmp[G_];
        #pragma unroll
        for (int g = 0; g < G_; g++)
            tmp[g] = __float2half_rn(x[(size_t)(b0 + g) * N_ + n]);
        *reinterpret_cast<uint4*>(bufA + (size_t)n * G_) =
            *reinterpret_cast<uint4*>(tmp);
    }
    __syncthreads();

    #pragma unroll 1
    for (int l = 0; l < L_; l++) {
        const __half* cur = (l & 1) ? bufB : bufA;
        __half*       nxt = (l & 1) ? bufA : bufB;
        const uint4*  srcv = reinterpret_cast<const uint4*>(g_src16) + (size_t)l * N_ * 2;
        const float4* wv   = reinterpret_cast<const float4*>(w) + (size_t)l * N_ * 4;
        const bool last = (l == L_ - 1);

        #pragma unroll 1
        for (int n = threadIdx.x; n < N_; n += THREADS_) {
            float acc[G_];
            #pragma unroll
            for (int g = 0; g < G_; g++) acc[g] = 0.0f;

            // k streamed in two halves of 8 to keep registers <= 64.
            half_k(cur, srcv[n * 2 + 0], wv + n * 4 + 0, acc);
            half_k(cur, srcv[n * 2 + 1], wv + n * 4 + 2, acc);

            float r[G_];
            #pragma unroll
            for (int g = 0; g < G_; g++)
                asm("tanh.approx.f32 %0, %1;" : "=f"(r[g]) : "f"(acc[g]));

            if (!last) {
                __half2 p[G_ / 2];
                #pragma unroll
                for (int g = 0; g < G_ / 2; g++)
                    p[g] = __floats2half2_rn(r[2 * g], r[2 * g + 1]);
                *reinterpret_cast<uint4*>(nxt + (size_t)n * G_) =
                    *reinterpret_cast<const uint4*>(p);
            } else {
                // Final layer: write fp32 straight to global.
                #pragma unroll
                for (int g = 0; g < G_; g++)
                    out[(size_t)(b0 + g) * N_ + n] = r[g];
            }
        }
        __syncthreads();
    }
}

extern "C" void kernel_launch(void* const* d_in, const int* in_sizes, int n_in,
                              void* d_out, int out_size) {
    const float* x   = (const float*)d_in[0];
    const int*   src = (const int*)d_in[1];
    const float* w   = (const float*)d_in[2];
    float*       out = (float*)d_out;

    // Pack indices to uint16 (deterministic, graph-capturable, no allocs).
    int total4 = (L_ * N_ * K_) / 4;
    prep_src16<<<(total4 + 255) / 256, 256>>>(src);

    size_t smem = (size_t)2 * N_ * G_ * sizeof(__half);  // 128 KB
    cudaFuncSetAttribute(genome_kernel,
                         cudaFuncAttributeMaxDynamicSharedMemorySize, (int)smem);
    genome_kernel<<<NBLOCKS_, THREADS_, smem>>>(x, w, out);
}

// round 4
// speedup vs baseline: 1.0062x; 1.0062x over previous
#include <cuda_runtime.h>
#include <cuda_fp16.h>
#include <cstdint>

#define B_      1024
#define N_      4096
#define L_      8
#define K_      16
#define G_      8            // batch rows per block
#define THREADS_ 1024
#define NBLOCKS_ (B_ / G_)   // 128

// Scratch: bank-schedule-permuted indices (uint16) and weights (fp32).
__device__ __align__(16) uint16_t g_src16[L_ * N_ * K_];   // 1 MB
__device__ __align__(16) float    g_wperm[L_ * N_ * K_];   // 2 MB

// For each (layer, n): counting-sort the 16 (src, w) pairs by bank-group
// (s & 7), then rotate by 2*(n mod 8). Within each quarter-warp octet of the
// main kernel, the 8 lanes then hit ~all-distinct bank-groups at every k-step,
// collapsing smem replay conflicts. Accumulation is commutative, so any
// per-(l,n) permutation of (src, w) pairs is exact.
__global__ void prep_sched(const int* __restrict__ src,
                           const float* __restrict__ w) {
    int t = blockIdx.x * blockDim.x + threadIdx.x;
    if (t >= L_ * N_) return;
    int n = t & (N_ - 1);
    const int*   sp = src + (size_t)t * K_;
    const float* wp = w   + (size_t)t * K_;

    uint16_t si[K_]; float wi[K_];
    int cnt[8] = {0, 0, 0, 0, 0, 0, 0, 0};
    #pragma unroll
    for (int k = 0; k < K_; k++) {
        int s = sp[k];
        si[k] = (uint16_t)s;
        wi[k] = wp[k];
        cnt[s & 7]++;
    }
    int off[8], acc = 0;
    #pragma unroll
    for (int b = 0; b < 8; b++) { off[b] = acc; acc += cnt[b]; }

    uint16_t ss[K_]; float ws[K_];
    #pragma unroll
    for (int k = 0; k < K_; k++) {
        int p = off[si[k] & 7]++;
        ss[p] = si[k];
        ws[p] = wi[k];
    }

    int r = 2 * (n & 7);   // lane-in-octet rotation (lane = n mod 32)
    uint16_t* so = g_src16 + (size_t)t * K_;
    float*    wo = g_wperm + (size_t)t * K_;
    #pragma unroll
    for (int kk = 0; kk < K_; kk++) {
        int p = (kk + r) & (K_ - 1);
        so[kk] = ss[p];
        wo[kk] = ws[p];
    }
}

// One gather index serves all G=8 batch rows: one LDS.128 of [s][0..7] fp16.
__device__ __forceinline__ void gather_fma(const __half* __restrict__ cur,
                                           uint32_t s, float wk, float* acc) {
    uint4 v = *reinterpret_cast<const uint4*>(cur + s * G_);
    float2 f;
    f = __half22float2(*reinterpret_cast<__half2*>(&v.x));
    acc[0] = fmaf(f.x, wk, acc[0]); acc[1] = fmaf(f.y, wk, acc[1]);
    f = __half22float2(*reinterpret_cast<__half2*>(&v.y));
    acc[2] = fmaf(f.x, wk, acc[2]); acc[3] = fmaf(f.y, wk, acc[3]);
    f = __half22float2(*reinterpret_cast<__half2*>(&v.z));
    acc[4] = fmaf(f.x, wk, acc[4]); acc[5] = fmaf(f.y, wk, acc[5]);
    f = __half22float2(*reinterpret_cast<__half2*>(&v.w));
    acc[6] = fmaf(f.x, wk, acc[6]); acc[7] = fmaf(f.y, wk, acc[7]);
}

__device__ __forceinline__ void half_k(const __half* __restrict__ cur,
                                       uint4 s, const float4* __restrict__ wv,
                                       float* acc) {
    float4 wa = wv[0];
    gather_fma(cur, s.x & 0xFFFFu, wa.x, acc);
    gather_fma(cur, s.x >> 16,     wa.y, acc);
    gather_fma(cur, s.y & 0xFFFFu, wa.z, acc);
    gather_fma(cur, s.y >> 16,     wa.w, acc);
    float4 wb = wv[1];
    gather_fma(cur, s.z & 0xFFFFu, wb.x, acc);
    gather_fma(cur, s.z >> 16,     wb.y, acc);
    gather_fma(cur, s.w & 0xFFFFu, wb.z, acc);
    gather_fma(cur, s.w >> 16,     wb.w, acc);
}

__global__ void __launch_bounds__(THREADS_, 1)
genome_kernel(const float* __restrict__ x, float* __restrict__ out) {
    extern __shared__ __half sm[];
    __half* bufA = sm;               // [N_][G_]
    __half* bufB = sm + N_ * G_;     // double buffer
    const int b0 = blockIdx.x * G_;

    for (int n = threadIdx.x; n < N_; n += THREADS_) {
        __half tmp[G_];
        #pragma unroll
        for (int g = 0; g < G_; g++)
            tmp[g] = __float2half_rn(x[(size_t)(b0 + g) * N_ + n]);
        *reinterpret_cast<uint4*>(bufA + (size_t)n * G_) =
            *reinterpret_cast<uint4*>(tmp);
    }
    __syncthreads();

    #pragma unroll 1
    for (int l = 0; l < L_; l++) {
        const __half* cur = (l & 1) ? bufB : bufA;
        __half*       nxt = (l & 1) ? bufA : bufB;
        const uint4*  srcv = reinterpret_cast<const uint4*>(g_src16) + (size_t)l * N_ * 2;
        const float4* wv   = reinterpret_cast<const float4*>(g_wperm) + (size_t)l * N_ * 4;
        const bool last = (l == L_ - 1);

        #pragma unroll 1
        for (int n = threadIdx.x; n < N_; n += THREADS_) {
            float acc[G_];
            #pragma unroll
            for (int g = 0; g < G_; g++) acc[g] = 0.0f;

            half_k(cur, srcv[n * 2 + 0], wv + n * 4 + 0, acc);
            half_k(cur, srcv[n * 2 + 1], wv + n * 4 + 2, acc);

            float r[G_];
            #pragma unroll
            for (int g = 0; g < G_; g++)
                asm("tanh.approx.f32 %0, %1;" : "=f"(r[g]) : "f"(acc[g]));

            if (!last) {
                __half2 p[G_ / 2];
                #pragma unroll
                for (int g = 0; g < G_ / 2; g++)
                    p[g] = __floats2half2_rn(r[2 * g], r[2 * g + 1]);
                *reinterpret_cast<uint4*>(nxt + (size_t)n * G_) =
                    *reinterpret_cast<const uint4*>(p);
            } else {
                #pragma unroll
                for (int g = 0; g < G_; g++)
                    out[(size_t)(b0 + g) * N_ + n] = r[g];
            }
        }
        __syncthreads();
    }
}

extern "C" void kernel_launch(void* const* d_in, const int* in_sizes, int n_in,
                              void* d_out, int out_size) {
    const float* x   = (const float*)d_in[0];
    const int*   src = (const int*)d_in[1];
    const float* w   = (const float*)d_in[2];
    float*       out = (float*)d_out;

    int total = L_ * N_;
    prep_sched<<<(total + 255) / 256, 256>>>(src, w);

    size_t smem = (size_t)2 * N_ * G_ * sizeof(__half);  // 128 KB
    cudaFuncSetAttribute(genome_kernel,
                         cudaFuncAttributeMaxDynamicSharedMemorySize, (int)smem);
    genome_kernel<<<NBLOCKS_, THREADS_, smem>>>(x, out);
}